// round 2
// baseline (speedup 1.0000x reference)
#include <cuda_runtime.h>
#include <cuda_bf16.h>
#include <mma.h>
#include <math.h>

using namespace nvcuda;

// Problem constants (fixed shapes from the reference)
#define C_DIM   256          // channels (K)
#define M_CLS   256          // classes  (N of GEMM)
#define HW      16384        // 128*128 pixels per image
#define N_PIX   262144       // 16*128*128
#define TILE_P  64           // pixels per CTA
#define KB      32           // K chunk per stage
#define NBLOCKS (N_PIX / TILE_P)   // 4096
#define INV_T   14.2857142857142857f   // 1/0.07

// smem leading dims (padded; all row strides multiples of 16 bytes)
#define LDA 72    // A stage: [KB][TILE_P + 8] bf16   (col-major A: A[m][k] at As[k*LDA+m])
#define LDB 40    // B stage: [M_CLS][KB + 8]  bf16   (col-major B: B[k][n] at Bs[n*LDB+k])
#define LDL 264   // logits:  [TILE_P][M_CLS + 8] f32

#define STAGE_A_BYTES (KB * LDA * 2)                    // 4608
#define LOGITS_BYTES  (TILE_P * LDL * 4)                // 67584
#define RED_OFF       LOGITS_BYTES
#define SMEM_BYTES    (LOGITS_BYTES + 64)               // 67648

__device__ float2 g_partials[NBLOCKS];

__global__ __launch_bounds__(256, 2)
void pcl_fused_kernel(const float* __restrict__ feats,
                      const float* __restrict__ queue,
                      const int*   __restrict__ labels)
{
    extern __shared__ char smem_raw[];
    __nv_bfloat16* As = (__nv_bfloat16*)smem_raw;                    // [KB][LDA]
    __nv_bfloat16* Bs = (__nv_bfloat16*)(smem_raw + STAGE_A_BYTES);  // [M_CLS][LDB]
    float*         Ls = (float*)smem_raw;                            // [TILE_P][LDL] (union w/ stage)
    float*         red = (float*)(smem_raw + RED_OFF);               // [16]

    const int tid  = threadIdx.x;
    const int warp = tid >> 5;
    const int lane = tid & 31;
    const int pix0 = blockIdx.x * TILE_P;

    // feats is [b, c, h, w]; pixel n -> (b = n/HW, hw = n%HW); TILE_P divides HW.
    const float* fbase = feats + (size_t)(pix0 / HW) * C_DIM * HW + (pix0 % HW);

    const int wm = warp & 1;    // pixel-dim warp coord (0..1)  -> offset wm*32
    const int wn = warp >> 1;   // class-dim warp coord (0..3)  -> offset wn*64

    wmma::fragment<wmma::accumulator, 16, 16, 16, float> acc[2][4];
    #pragma unroll
    for (int i = 0; i < 2; i++)
        #pragma unroll
        for (int j = 0; j < 4; j++)
            wmma::fill_fragment(acc[i][j], 0.0f);

    const int pixl = tid & 63;   // pixel lane for A staging
    const int chb  = tid >> 6;   // channel group (0..3)

    #pragma unroll 1
    for (int ks = 0; ks < C_DIM / KB; ks++) {
        __syncthreads();   // previous MMA consumed smem

        // ---- stage A: 32 channels x 64 pixels (coalesced 256B per 64-thread group) ----
        #pragma unroll
        for (int it = 0; it < 8; it++) {
            int ch = chb + it * 4;                 // 0..31, all covered
            float v = fbase[(size_t)(ks * KB + ch) * HW + pixl];
            As[ch * LDA + pixl] = __float2bfloat16(v);
        }
        // ---- stage B: 256 classes x 32 channels (128B coalesced per warp) ----
        #pragma unroll
        for (int it = 0; it < 32; it++) {
            int cls = warp + 8 * it;               // 0..255
            float v = queue[cls * C_DIM + ks * KB + lane];
            Bs[cls * LDB + lane] = __float2bfloat16(v);
        }
        __syncthreads();

        // ---- MMA: warp tile 32 pix x 64 cls, two k16 sub-steps ----
        #pragma unroll
        for (int kf = 0; kf < KB / 16; kf++) {
            wmma::fragment<wmma::matrix_a, 16, 16, 16, __nv_bfloat16, wmma::col_major> af[2];
            wmma::fragment<wmma::matrix_b, 16, 16, 16, __nv_bfloat16, wmma::col_major> bf[4];
            #pragma unroll
            for (int i = 0; i < 2; i++)
                wmma::load_matrix_sync(af[i], As + kf * 16 * LDA + wm * 32 + i * 16, LDA);
            #pragma unroll
            for (int j = 0; j < 4; j++)
                wmma::load_matrix_sync(bf[j], Bs + (wn * 64 + j * 16) * LDB + kf * 16, LDB);
            #pragma unroll
            for (int i = 0; i < 2; i++)
                #pragma unroll
                for (int j = 0; j < 4; j++)
                    wmma::mma_sync(acc[i][j], af[i], bf[j], acc[i][j]);
        }
    }

    __syncthreads();  // done with stage smem; reuse as logits tile
    #pragma unroll
    for (int i = 0; i < 2; i++)
        #pragma unroll
        for (int j = 0; j < 4; j++)
            wmma::store_matrix_sync(Ls + (wm * 32 + i * 16) * LDL + wn * 64 + j * 16,
                                    acc[i][j], LDL, wmma::mem_row_major);
    __syncthreads();

    // ---- fused epilogue: exp + mask + per-pixel sums ----
    // thread -> (pixel, 64-class chunk): 4 threads (one quad) per pixel
    const int pix = tid >> 2;
    const int qd  = tid & 3;
    const float* lrow = Ls + pix * LDL + qd * 64;
    const int4*  lab  = (const int4*)(labels + (size_t)(pix0 + pix) * M_CLS + qd * 64);

    float sn = 0.0f, sp = 0.0f;
    #pragma unroll
    for (int j = 0; j < 16; j++) {
        int4   l4 = lab[j];
        float4 d4 = ((const float4*)lrow)[j];
        {
            float s = d4.x * INV_T; float e = __expf(l4.x ? -s : s);
            if (l4.x) sp += e; else sn += e;
        }
        {
            float s = d4.y * INV_T; float e = __expf(l4.y ? -s : s);
            if (l4.y) sp += e; else sn += e;
        }
        {
            float s = d4.z * INV_T; float e = __expf(l4.z ? -s : s);
            if (l4.z) sp += e; else sn += e;
        }
        {
            float s = d4.w * INV_T; float e = __expf(l4.w ? -s : s);
            if (l4.w) sp += e; else sn += e;
        }
    }
    // reduce the quad (lanes t, t^1, t^2 share a pixel)
    sn += __shfl_xor_sync(0xFFFFFFFFu, sn, 1);
    sn += __shfl_xor_sync(0xFFFFFFFFu, sn, 2);
    sp += __shfl_xor_sync(0xFFFFFFFFu, sp, 1);
    sp += __shfl_xor_sync(0xFFFFFFFFu, sp, 2);

    float th_loss = 0.0f, th_cnt = 0.0f;
    if (qd == 0) {
        float x    = sn * sp;
        float loss = logf(x + 1.0f);            // matches reference: log(sum_neg*sum_pos + 1)
        th_loss = loss;
        th_cnt  = (loss != 0.0f) ? 1.0f : 0.0f;
    }
    // block reduction (fixed tree -> deterministic)
    #pragma unroll
    for (int o = 16; o > 0; o >>= 1) {
        th_loss += __shfl_xor_sync(0xFFFFFFFFu, th_loss, o);
        th_cnt  += __shfl_xor_sync(0xFFFFFFFFu, th_cnt,  o);
    }
    if (lane == 0) { red[warp * 2] = th_loss; red[warp * 2 + 1] = th_cnt; }
    __syncthreads();
    if (tid == 0) {
        float s = 0.0f, c = 0.0f;
        #pragma unroll
        for (int w = 0; w < 8; w++) { s += red[2 * w]; c += red[2 * w + 1]; }
        g_partials[blockIdx.x] = make_float2(s, c);
    }
}

__global__ void pcl_reduce_kernel(float* __restrict__ out)
{
    __shared__ double ssum[256];
    __shared__ float  scnt[256];
    double s = 0.0;
    float  c = 0.0f;
    for (int i = threadIdx.x; i < NBLOCKS; i += 256) {
        float2 p = g_partials[i];
        s += (double)p.x;
        c += p.y;
    }
    ssum[threadIdx.x] = s;
    scnt[threadIdx.x] = c;
    __syncthreads();
    for (int o = 128; o > 0; o >>= 1) {
        if (threadIdx.x < o) {
            ssum[threadIdx.x] += ssum[threadIdx.x + o];
            scnt[threadIdx.x] += scnt[threadIdx.x + o];
        }
        __syncthreads();
    }
    if (threadIdx.x == 0) {
        float cnt = scnt[0];
        out[0] = (cnt == 0.0f) ? 0.0f : (float)(ssum[0] / (double)fmaxf(cnt, 1.0f));
    }
}

extern "C" void kernel_launch(void* const* d_in, const int* in_sizes, int n_in,
                              void* d_out, int out_size)
{
    // Inputs in metadata.txt order (== reference setup_inputs order):
    //   d_in[0] = feats  (float32, 16*256*128*128 = 67108864 elems)
    //   d_in[1] = queue  (float32, 256*256 = 65536 elems)
    //   d_in[2] = labels (int32,   262144*256 = 67108864 elems)
    // NOTE: feats and labels have IDENTICAL element counts — positional, not
    // size-based, identification is required.
    const float* feats  = (const float*)d_in[0];
    const float* queue  = (const float*)d_in[1];
    const int*   labels = (const int*)d_in[2];

    cudaFuncSetAttribute(pcl_fused_kernel,
                         cudaFuncAttributeMaxDynamicSharedMemorySize, SMEM_BYTES);

    pcl_fused_kernel<<<NBLOCKS, 256, SMEM_BYTES>>>(feats, queue, labels);
    pcl_reduce_kernel<<<1, 256>>>((float*)d_out);
}